// round 3
// baseline (speedup 1.0000x reference)
#include <cuda_runtime.h>
#include <cstdint>

typedef unsigned long long u64;
typedef unsigned int u32;

#define NN 8192
#define NW 128               // mask row stride in 64-bit words
#define NBK 4096             // score buckets
#define NCELL 256            // 16x16 spatial grid
#define CS 80.0f
#define THR 0.7f
#define IOU_THR 0.5f
#define EPSF 1e-9f
#define SCALER_F 2.740625f   // 3508/1280
#define NBLK 148
#define TPB 256

// ---------------- device scratch -------------------------------------------
__device__ u32 g_barCount;
__device__ int g_V;
__device__ u32 g_inv[NN];
__device__ int g_bucket[NN];
__device__ u32 g_hist[NBK];
__device__ u32 g_bstart[NBK + 1];
__device__ u32 g_bfill[NBK];
__device__ u64 g_skey[NN];
__device__ float4 g_box[NN];
__device__ float2 g_conf[NN];
__device__ float  g_area[NN];
__device__ int g_cellOf[NN];
__device__ u32 g_cellCount[NCELL];
__device__ u32 g_cellStart[NCELL + 1];
__device__ u32 g_cellFill[NCELL];
__device__ int g_cellList[NN];
__device__ u64 g_mask[(size_t)NN * NW];
__device__ u64 g_keep[NW];

// ---------------- init: reset counters each replay --------------------------
__global__ void init_kernel() {
    int t = blockIdx.x * TPB + threadIdx.x;
    if (t < NBK)   g_hist[t] = 0;
    if (t < NCELL) g_cellCount[t] = 0;
    if (t == 0) { g_V = 0; g_barCount = 0; }
}

// ---------------- software grid barrier -------------------------------------
__device__ __forceinline__ void gridbar(u32 &target) {
    __syncthreads();
    if (threadIdx.x == 0) {
        __threadfence();
        atomicAdd(&g_barCount, 1u);
        while (atomicAdd(&g_barCount, 0u) < target) __nanosleep(64);
    }
    __syncthreads();
    target += NBLK;
}

// ---------------- the whole pipeline in one launch ---------------------------
__global__ __launch_bounds__(TPB, 1)
void mega_kernel(const float* __restrict__ conf, const float* __restrict__ boxes,
                 float* __restrict__ out) {
    const int tid = threadIdx.x;
    const int gtid = blockIdx.x * TPB + tid;
    u32 bar = NBLK;

    __shared__ u32 sscan[TPB];
    __shared__ u64 keepS[NW];
    __shared__ u64 diag[64];
    __shared__ u64 curw;

    // ---- A: keys + bucket histogram + valid count ----
    if (gtid < NN) {
        float2 c = __ldg(&((const float2*)conf)[gtid]);
        bool valid = (c.x > THR) || (c.y > THR);
        float s = fmaxf(c.x, c.y);
        u32 inv = valid ? ~(__float_as_uint(s) | 0x80000000u) : 0xFFFFFFFFu;
        g_inv[gtid] = inv;
        if (valid) {
            // valid scores lie in (0.7, 1]; monotone affine bucket map
            u32 b = (u32)((1.0f - s) * 13653.0f);
            if (b > NBK - 1) b = NBK - 1;
            g_bucket[gtid] = (int)b;
            atomicAdd(&g_hist[b], 1u);
        }
        u32 vb = __ballot_sync(0xFFFFFFFFu, valid);
        if ((tid & 31) == 0 && vb) atomicAdd(&g_V, (int)__popc(vb));
    }
    gridbar(bar);

    // ---- B: exclusive scan of 4096 bucket counts (block 0) ----
    if (blockIdx.x == 0) {
        u32 vals[16]; u32 sum = 0;
        int base = tid * 16;
        #pragma unroll
        for (int k = 0; k < 16; k++) { vals[k] = __ldcg(&g_hist[base + k]); sum += vals[k]; }
        sscan[tid] = sum;
        __syncthreads();
        for (int off = 1; off < TPB; off <<= 1) {
            u32 cur = sscan[tid];
            u32 add = (tid >= off) ? sscan[tid - off] : 0u;
            __syncthreads();
            sscan[tid] = cur + add;
            __syncthreads();
        }
        u32 run = sscan[tid] - sum;
        #pragma unroll
        for (int k = 0; k < 16; k++) { g_bstart[base + k] = run; g_bfill[base + k] = run; run += vals[k]; }
        if (tid == TPB - 1) g_bstart[NBK] = run;
    }
    gridbar(bar);

    // ---- C: scatter into buckets ----
    if (gtid < NN) {
        u32 inv = g_inv[gtid];
        if (inv != 0xFFFFFFFFu) {
            u32 pos = atomicAdd(&g_bfill[g_bucket[gtid]], 1u);
            g_skey[pos] = ((u64)inv << 32) | (u32)gtid;
        }
    }
    gridbar(bar);

    // ---- D: per-bucket stable sort + gather + cell counting ----
    if (gtid < NBK) {
        int s = (int)__ldcg(&g_bstart[gtid]);
        int e = (int)__ldcg(&g_bstart[gtid + 1]);
        int n = e - s;
        if (n > 1) {
            if (n <= 16) {
                u64 loc[16];
                for (int k = 0; k < n; k++) loc[k] = __ldcg(&g_skey[s + k]);
                for (int a = 1; a < n; a++) {
                    u64 key = loc[a]; int c = a;
                    while (c > 0 && loc[c - 1] > key) { loc[c] = loc[c - 1]; c--; }
                    loc[c] = key;
                }
                for (int k = 0; k < n; k++) g_skey[s + k] = loc[k];
            } else {
                for (int a = s + 1; a < e; a++) {
                    u64 key = __ldcg(&g_skey[a]); int c = a;
                    while (c > s) {
                        u64 pk = __ldcg(&g_skey[c - 1]);
                        if (pk > key) { g_skey[c] = pk; c--; } else break;
                    }
                    g_skey[c] = key;
                }
            }
        }
        for (int p = s; p < e; p++) {
            u64 key = __ldcg(&g_skey[p]);            // same-thread after own stores: coherent
            u32 idx = (u32)key;
            float4 bb = __ldg(&((const float4*)boxes)[idx]);
            g_box[p] = bb;
            g_area[p] = (bb.z - bb.x) * (bb.w - bb.y);
            g_conf[p] = __ldg(&((const float2*)conf)[idx]);
            int cx = (int)(bb.x * (1.0f / CS)); if (cx > 15) cx = 15;
            int cy = (int)(bb.y * (1.0f / CS)); if (cy > 15) cy = 15;
            int cell = cy * 16 + cx;
            g_cellOf[p] = cell;
            atomicAdd(&g_cellCount[cell], 1u);
        }
    }
    gridbar(bar);

    // ---- E: scan of 256 cell counts (block 0, 256 threads == NCELL) ----
    if (blockIdx.x == 0) {
        u32 v = __ldcg(&g_cellCount[tid]);
        sscan[tid] = v;
        __syncthreads();
        for (int off = 1; off < TPB; off <<= 1) {
            u32 cur = sscan[tid];
            u32 add = (tid >= off) ? sscan[tid - off] : 0u;
            __syncthreads();
            sscan[tid] = cur + add;
            __syncthreads();
        }
        u32 excl = sscan[tid] - v;
        g_cellStart[tid] = excl;
        g_cellFill[tid] = excl;
        if (tid == TPB - 1) g_cellStart[NCELL] = sscan[tid];
    }
    gridbar(bar);

    // ---- F: scatter sorted positions into cells ----
    const int V = __ldcg(&g_V);
    if (gtid < V) {
        int c = __ldcg(&g_cellOf[gtid]);
        u32 pos = atomicAdd(&g_cellFill[c], 1u);
        g_cellList[pos] = gtid;
    }
    gridbar(bar);

    // ---- G: sparse suppression mask via spatial hash ----
    if (gtid < V) {
        const int p = gtid;
        const int nb = (V + 63) >> 6;
        float4 bp = __ldcg(&g_box[p]);
        float ap = __ldcg(&g_area[p]);
        u64* row = &g_mask[(size_t)p * NW];
        for (int w = p >> 6; w < nb; w++) row[w] = 0;

        const float r = 1.0f / CS;
        int cx0 = (int)fmaxf(floorf((bp.x - 81.0f) * r), 0.0f);
        int cx1 = (int)fminf(floorf(bp.z * r), 15.0f);
        int cy0 = (int)fmaxf(floorf((bp.y - 81.0f) * r), 0.0f);
        int cy1 = (int)fminf(floorf(bp.w * r), 15.0f);

        for (int cy = cy0; cy <= cy1; cy++)
        for (int cx = cx0; cx <= cx1; cx++) {
            int c = cy * 16 + cx;
            int s = (int)__ldcg(&g_cellStart[c]), e = (int)__ldcg(&g_cellStart[c + 1]);
            for (int t = s; t < e; t++) {
                int q = __ldcg(&g_cellList[t]);
                if (q <= p) continue;
                float4 bq = __ldcg(&g_box[q]);
                float iw = fmaxf(fminf(bp.z, bq.z) - fmaxf(bp.x, bq.x), 0.0f);
                float ih = fmaxf(fminf(bp.w, bq.w) - fmaxf(bp.y, bq.y), 0.0f);
                float inter = iw * ih;
                if (inter > 0.0f) {
                    float iou = inter / (ap + __ldcg(&g_area[q]) - inter + EPSF);
                    if (iou > IOU_THR) row[q >> 6] |= (1ull << (q & 63));
                }
            }
        }
    }
    gridbar(bar);

    // ---- H: greedy bitmask reduce (block 0) ----
    if (blockIdx.x == 0) {
        const int nb = (V + 63) >> 6;
        for (int w = tid; w < NW; w += TPB) {
            int base = w * 64;
            u64 k;
            if (base + 64 <= V)      k = ~0ull;
            else if (base >= V)      k = 0ull;
            else                     k = (1ull << (V - base)) - 1ull;
            keepS[w] = k;
        }
        __syncthreads();
        for (int b = 0; b < nb; b++) {
            if (tid < 64) diag[tid] = __ldcg(&g_mask[(size_t)(b * 64 + tid) * NW + b]);
            __syncthreads();
            if (tid == 0) {
                u64 kw = keepS[b];
                #pragma unroll
                for (int i = 0; i < 64; i++) {
                    u64 bit = (kw >> i) & 1ull;
                    kw &= ~(diag[i] & (0ull - bit));   // branchless sequential
                }
                keepS[b] = kw;
                curw = kw;
            }
            __syncthreads();
            u64 kw = curw;
            for (int w = b + 1 + tid; w < nb; w += TPB) {
                u64 rem = 0, t2 = kw;
                while (t2) {
                    int i = __ffsll((long long)t2) - 1;
                    t2 &= t2 - 1;
                    rem |= __ldcg(&g_mask[(size_t)(b * 64 + i) * NW + w]);
                }
                keepS[w] &= ~rem;
            }
            __syncthreads();
        }
        for (int w = tid; w < NW; w += TPB) g_keep[w] = keepS[w];
    }
    gridbar(bar);

    // ---- I: output ----
    if (gtid < NN) {
        float2* o = (float2*)(out + (size_t)gtid * 6);
        if (gtid < V) {
            float kf = ((__ldcg(&g_keep[gtid >> 6]) >> (gtid & 63)) & 1ull) ? 1.0f : 0.0f;
            float4 bb = __ldcg(&g_box[gtid]);
            float2 cc = __ldcg(&g_conf[gtid]);
            o[0] = make_float2(bb.x * SCALER_F * kf, bb.y * SCALER_F * kf);
            o[1] = make_float2(bb.z * SCALER_F * kf, bb.w * SCALER_F * kf);
            o[2] = make_float2(cc.x * kf, cc.y * kf);
        } else {
            o[0] = make_float2(0.0f, 0.0f);
            o[1] = make_float2(0.0f, 0.0f);
            o[2] = make_float2(0.0f, 0.0f);
        }
    }
}

// ---------------- launch -----------------------------------------------------
extern "C" void kernel_launch(void* const* d_in, const int* in_sizes, int n_in,
                              void* d_out, int out_size) {
    const float* conf  = (const float*)d_in[0];   // (N, 2)
    const float* boxes = (const float*)d_in[1];   // (N, 4)
    if (n_in >= 2 && in_sizes[0] == NN * 4) {     // order by size, just in case
        boxes = (const float*)d_in[0];
        conf  = (const float*)d_in[1];
    }
    float* out = (float*)d_out;

    init_kernel<<<16, TPB>>>();
    mega_kernel<<<NBLK, TPB>>>(conf, boxes, out);
}